// round 6
// baseline (speedup 1.0000x reference)
#include <cuda_runtime.h>
#include <math.h>
#include <stdint.h>

#define BB 1024
#define TT 80
#define EE 100
#define UU 256
#define K1 384          // 256 (h) + 128 (x padded to 128)
#define K2 512          // 256 (h2) + 256 (h1)
#define NTOT 1024       // 4 gates * 256 units (permuted layout, see pack_w)
#define HS (UU*BB)

// dynamic smem layout (floats):
//   SA[2][32][72]   double-buffered A tile   (2*2304)
//   SB[2][128][36]  double-buffered B tile   (2*4608)
//   sBias[4][32]
#define SA_STRIDE 2304
#define SB_STRIDE 4608
#define SB_OFF    (2*SA_STRIDE)
#define BIAS_OFF  (SB_OFF + 2*SB_STRIDE)
#define SMEM_FLOATS (BIAS_OFF + 128)
#define SMEM_BYTES  (SMEM_FLOATS * 4)

// ---------------- device scratch ----------------
__device__ float g_XT[(size_t)TT * 128 * BB];    // [t][e][b], e padded to 128, tf32-rounded
__device__ float g_Wp1[(size_t)NTOT * K1];       // [n_packed][k]
__device__ float g_Wp2[(size_t)NTOT * K2];
__device__ float g_h1T[2][HS];                   // [u][b]
__device__ float g_h2T[2][HS];
__device__ float g_c1T[HS];
__device__ float g_c2T[HS];

// ---------------- helpers ----------------
__device__ __forceinline__ float to_tf32(float x) {
    uint32_t u;
    asm("cvt.rna.tf32.f32 %0, %1;" : "=r"(u) : "f"(x));
    return __uint_as_float(u);
}
__device__ __forceinline__ float sigm(float x) {
    return __fdividef(1.0f, 1.0f + __expf(-x));
}
__device__ __forceinline__ float tanh_(float x) {
    return __fdividef(2.0f, 1.0f + __expf(-2.0f * x)) - 1.0f;
}
__device__ __forceinline__ void mma8(float& c0, float& c1, float& c2, float& c3,
                                     uint32_t a0, uint32_t a1, uint32_t a2, uint32_t a3,
                                     uint32_t b0, uint32_t b1) {
    asm volatile(
        "mma.sync.aligned.m16n8k8.row.col.f32.tf32.tf32.f32 "
        "{%0,%1,%2,%3}, {%4,%5,%6,%7}, {%8,%9}, {%0,%1,%2,%3};"
        : "+f"(c0), "+f"(c1), "+f"(c2), "+f"(c3)
        : "r"(a0), "r"(a1), "r"(a2), "r"(a3), "r"(b0), "r"(b1));
}

// ---------------- init kernels ----------------
__global__ void gather_x(const int* __restrict__ tokens, const float* __restrict__ emb) {
    size_t idx = (size_t)blockIdx.x * 256 + threadIdx.x;
    if (idx >= (size_t)TT * 128 * BB) return;
    int b  = idx & (BB - 1);
    int te = (int)(idx >> 10);
    int e  = te & 127;
    int t  = te >> 7;
    float v = 0.0f;
    if (e < EE) v = emb[(size_t)tokens[b * TT + t] * EE + e];
    g_XT[idx] = to_tf32(v);
}

// Packed layout: CTA n-tile = 128 cols = 4 warps x 32. Within a warp's 32 cols:
//   col = j*8 + q*2 + r,  j=0..3, q=0..3 (lane quad), r=0..1
//   unit_local = (j&1)*4 + q  (8 units per warp),  gate = (j>>1)*2 + r
// so each mma lane (q = lane&3) owns all 4 gates of its units in its own accumulators.
__global__ void pack_w(const float* __restrict__ wf1, const float* __restrict__ wi1,
                       const float* __restrict__ wc1, const float* __restrict__ wo1,
                       const float* __restrict__ wf2, const float* __restrict__ wi2,
                       const float* __restrict__ wc2, const float* __restrict__ wo2) {
    int idx = blockIdx.x * 256 + threadIdx.x;
    const int tot1 = NTOT * K1;
    int P, k, which;
    if (idx < tot1) { P = idx / K1; k = idx % K1; which = 1; }
    else if (idx < tot1 + NTOT * K2) {
        int j2 = idx - tot1; P = j2 / K2; k = j2 % K2; which = 2;
    } else return;
    int ny  = P >> 7;            // CTA n-tile (32 units each)
    int rem = P & 127;
    int wn  = rem >> 5;          // warp within CTA (8 units each)
    int col = rem & 31;
    int j = col >> 3, q = (col >> 1) & 3, r = col & 1;
    int u = ny * 32 + wn * 8 + (j & 1) * 4 + q;
    int g = (j >> 1) * 2 + r;
    if (which == 1) {
        float v = 0.0f;
        if (k < UU + EE) {
            const float* w = (g == 0) ? wf1 : (g == 1) ? wi1 : (g == 2) ? wc1 : wo1;
            v = w[(size_t)k * UU + u];
        }
        g_Wp1[idx] = to_tf32(v);
    } else {
        const float* w = (g == 0) ? wf2 : (g == 1) ? wi2 : (g == 2) ? wc2 : wo2;
        g_Wp2[(size_t)P * K2 + k] = to_tf32(w[(size_t)k * UU + u]);
    }
}

__global__ void zero_state() {
    int idx = blockIdx.x * 256 + threadIdx.x;
    if (idx < HS) {
        g_h1T[0][idx] = 0.0f;
        g_h2T[0][idx] = 0.0f;
        g_c1T[idx]    = 0.0f;
        g_c2T[idx]    = 0.0f;
    }
}

// ---------------- LSTM tile: 64 batch x 32 units x 4 gates via mma.sync tf32 ----------------
template <int KP>
__device__ __forceinline__ void lstm_tile(
    const float* __restrict__ hT, const float* __restrict__ xT,
    const float* __restrict__ Wp,
    const float* __restrict__ bfv, const float* __restrict__ biv,
    const float* __restrict__ bcv, const float* __restrict__ bov,
    float* __restrict__ hoT, float* __restrict__ cT,
    float* __restrict__ sm) {

    float* sa    = sm;                 // [2][32][72]
    float* sb    = sm + SB_OFF;        // [2][128][36]
    float* sBias = sm + BIAS_OFF;      // [4][32]

    const int tid  = threadIdx.x;
    const int lane = tid & 31, wid = tid >> 5;
    const int wm = wid >> 2, wn = wid & 3;       // 2m x 4n warps
    const int rr = lane >> 2, kq = lane & 3;
    const int b0 = blockIdx.x * 64;
    const int n0 = blockIdx.y * 128;             // packed-col base
    const int u0 = blockIdx.y * 32;              // unit base

    // stage biases for this CTA's 32 units
    if (tid < 128) {
        int g = tid >> 5, ui = tid & 31;
        const float* bsrc = (g == 0) ? bfv : (g == 1) ? biv : (g == 2) ? bcv : bov;
        sBias[g * 32 + ui] = bsrc[u0 + ui];
    }

    constexpr int NC = KP / 32;

    // loader indices
    const int ak = tid >> 3, am = tid & 7;       // A: k row (0..31), float4 col base
    const int bn = tid >> 1, bh = tid & 1;       // B: n row (0..127), k half

    float4 pa[2], pb[4];
    auto prefetch = [&](int c) {
        const float* asrc = (c * 32 < UU) ? (hT + (size_t)(c * 32) * BB + b0)
                                          : (xT + (size_t)(c * 32 - UU) * BB + b0);
        const float* arow = asrc + (size_t)ak * BB + am * 4;
        pa[0] = *(const float4*)(arow);
        pa[1] = *(const float4*)(arow + 32);
        const float* wrow = Wp + (size_t)(n0 + bn) * KP + c * 32 + bh * 16;
#pragma unroll
        for (int i = 0; i < 4; ++i) pb[i] = *(const float4*)(wrow + i * 4);
    };
    auto store_s = [&](int buf) {
        float* sA = sa + buf * SA_STRIDE;
        *(float4*)&sA[ak * 72 + am * 4]      = pa[0];
        *(float4*)&sA[ak * 72 + am * 4 + 32] = pa[1];
        float* sB = sb + buf * SB_STRIDE;
#pragma unroll
        for (int i = 0; i < 4; ++i) *(float4*)&sB[bn * 36 + bh * 16 + i * 4] = pb[i];
    };

    float acc[2][4][4];
#pragma unroll
    for (int mi = 0; mi < 2; ++mi)
#pragma unroll
        for (int j = 0; j < 4; ++j)
#pragma unroll
            for (int e = 0; e < 4; ++e) acc[mi][j][e] = 0.0f;

    prefetch(0);
    store_s(0);
    __syncthreads();

    for (int c = 0; c < NC; ++c) {
        const int buf = c & 1;
        if (c + 1 < NC) prefetch(c + 1);

        const float* sA = sa + buf * SA_STRIDE;
        const float* sB = sb + buf * SB_STRIDE;
#pragma unroll
        for (int ks = 0; ks < 4; ++ks) {
            const int k0 = ks * 8;
            uint32_t a[2][4];
#pragma unroll
            for (int mi = 0; mi < 2; ++mi) {
                const int mb = wm * 32 + mi * 16 + rr;
                a[mi][0] = __float_as_uint(sA[(k0 + kq    ) * 72 + mb    ]);
                a[mi][1] = __float_as_uint(sA[(k0 + kq    ) * 72 + mb + 8]);
                a[mi][2] = __float_as_uint(sA[(k0 + kq + 4) * 72 + mb    ]);
                a[mi][3] = __float_as_uint(sA[(k0 + kq + 4) * 72 + mb + 8]);
            }
#pragma unroll
            for (int j = 0; j < 4; ++j) {
                const int nrow = wn * 32 + j * 8 + rr;
                uint32_t b0r = __float_as_uint(sB[nrow * 36 + k0 + kq    ]);
                uint32_t b1r = __float_as_uint(sB[nrow * 36 + k0 + kq + 4]);
#pragma unroll
                for (int mi = 0; mi < 2; ++mi)
                    mma8(acc[mi][j][0], acc[mi][j][1], acc[mi][j][2], acc[mi][j][3],
                         a[mi][0], a[mi][1], a[mi][2], a[mi][3], b0r, b1r);
            }
        }
        if (c + 1 < NC) {
            store_s(buf ^ 1);
            __syncthreads();
        }
    }

    // ---- epilogue: all 4 gates of each owned unit live in this lane's accs ----
    const int q = lane & 3;
#pragma unroll
    for (int mi = 0; mi < 2; ++mi) {
#pragma unroll
        for (int ub = 0; ub < 2; ++ub) {
            const int u_in = wn * 8 + ub * 4 + q;
            const int u = u0 + u_in;
            const float bf_ = sBias[0 * 32 + u_in], bi_ = sBias[1 * 32 + u_in];
            const float bc_ = sBias[2 * 32 + u_in], bo_ = sBias[3 * 32 + u_in];
#pragma unroll
            for (int rh = 0; rh < 2; ++rh) {
                const int b = b0 + wm * 32 + mi * 16 + rh * 8 + rr;
                float pf = acc[mi][ub    ][rh * 2 + 0] + bf_;
                float pi = acc[mi][ub    ][rh * 2 + 1] + bi_;
                float pc = acc[mi][ub + 2][rh * 2 + 0] + bc_;
                float po = acc[mi][ub + 2][rh * 2 + 1] + bo_;
                size_t off = (size_t)u * BB + b;
                float cn = sigm(pf) * cT[off] + sigm(pi) * tanh_(pc);
                cT[off]  = cn;
                hoT[off] = to_tf32(sigm(po) * tanh_(cn));
            }
        }
    }
}

// ---------------- fused step kernel: z=0 -> layer2(k-1), z=1 -> layer1(k) ----------------
__global__ __launch_bounds__(256, 2)
void step_kernel(
    int do1, const float* __restrict__ h1i, float* __restrict__ h1o,
    float* __restrict__ c1, const float* __restrict__ x1,
    const float* __restrict__ Wp1,
    const float* __restrict__ bf1, const float* __restrict__ bi1,
    const float* __restrict__ bc1, const float* __restrict__ bo1,
    int do2, const float* __restrict__ h2i, float* __restrict__ h2o,
    float* __restrict__ c2, const float* __restrict__ x2,
    const float* __restrict__ Wp2,
    const float* __restrict__ bf2, const float* __restrict__ bi2,
    const float* __restrict__ bc2, const float* __restrict__ bo2) {

    extern __shared__ float sm[];

    if (blockIdx.z == 1) {
        if (!do1) return;
        lstm_tile<K1>(h1i, x1, Wp1, bf1, bi1, bc1, bo1, h1o, c1, sm);
    } else {
        if (!do2) return;
        lstm_tile<K2>(h2i, x2, Wp2, bf2, bi2, bc2, bo2, h2o, c2, sm);
    }
}

// ---------------- output head ----------------
__global__ void final_kernel(const float* __restrict__ h2T,
                             const float* __restrict__ w_out,
                             const float* __restrict__ b_out,
                             float* __restrict__ out) {
    int b = blockIdx.x * 256 + threadIdx.x;
    float s = 0.0f;
#pragma unroll 8
    for (int u = 0; u < UU; ++u) s += h2T[(size_t)u * BB + b] * w_out[u];
    out[b] = __fdividef(1.0f, 1.0f + __expf(-(s + b_out[0])));
}

// ---------------- launch ----------------
extern "C" void kernel_launch(void* const* d_in, const int* in_sizes, int n_in,
                              void* d_out, int out_size) {
    const int*   tokens = (const int*)d_in[0];
    const float* emb    = (const float*)d_in[1];
    const float* wf1 = (const float*)d_in[2];  const float* bf1 = (const float*)d_in[3];
    const float* wi1 = (const float*)d_in[4];  const float* bi1 = (const float*)d_in[5];
    const float* wc1 = (const float*)d_in[6];  const float* bc1 = (const float*)d_in[7];
    const float* wo1 = (const float*)d_in[8];  const float* bo1 = (const float*)d_in[9];
    const float* wf2 = (const float*)d_in[10]; const float* bf2 = (const float*)d_in[11];
    const float* wi2 = (const float*)d_in[12]; const float* bi2 = (const float*)d_in[13];
    const float* wc2 = (const float*)d_in[14]; const float* bc2 = (const float*)d_in[15];
    const float* wo2 = (const float*)d_in[16]; const float* bo2 = (const float*)d_in[17];
    const float* w_out = (const float*)d_in[18];
    const float* b_out = (const float*)d_in[19];
    float* out = (float*)d_out;

    float *pXT, *pW1, *pW2, *ph1, *pc1, *ph2, *pc2;
    cudaGetSymbolAddress((void**)&pXT, g_XT);
    cudaGetSymbolAddress((void**)&pW1, g_Wp1);
    cudaGetSymbolAddress((void**)&pW2, g_Wp2);
    cudaGetSymbolAddress((void**)&ph1, g_h1T);
    cudaGetSymbolAddress((void**)&pc1, g_c1T);
    cudaGetSymbolAddress((void**)&ph2, g_h2T);
    cudaGetSymbolAddress((void**)&pc2, g_c2T);

    cudaFuncSetAttribute(step_kernel,
                         cudaFuncAttributeMaxDynamicSharedMemorySize, SMEM_BYTES);

    {
        size_t totx = (size_t)TT * 128 * BB;
        gather_x<<<(unsigned)((totx + 255) / 256), 256>>>(tokens, emb);
        int totw = NTOT * K1 + NTOT * K2;
        pack_w<<<(totw + 255) / 256, 256>>>(wf1, wi1, wc1, wo1, wf2, wi2, wc2, wo2);
        zero_state<<<(HS + 255) / 256, 256>>>();
    }

    // Pipelined schedule: launch k runs layer1(step k) and layer2(step k-1).
    dim3 grid(BB / 64, NTOT / 128, 2);      // 16 x 8 x 2 = 256 CTAs
    for (int k = 0; k <= TT; k++) {
        int do1 = (k < TT) ? 1 : 0;
        int do2 = (k >= 1) ? 1 : 0;
        const float* h1i = ph1 + (k & 1) * HS;          // h1(k-1)
        float*       h1o = ph1 + ((k + 1) & 1) * HS;    // h1(k)
        const float* x1  = pXT + (size_t)((k < TT) ? k : 0) * 128 * BB;
        const float* h2i = ph2 + ((k + 1) & 1) * HS;    // h2(k-2)
        float*       h2o = ph2 + (k & 1) * HS;          // h2(k-1)
        const float* x2  = ph1 + (k & 1) * HS;          // h1(k-1)
        step_kernel<<<grid, 256, SMEM_BYTES>>>(
            do1, h1i, h1o, pc1, x1, pW1, bf1, bi1, bc1, bo1,
            do2, h2i, h2o, pc2, x2, pW2, bf2, bi2, bc2, bo2);
    }

    // h2(79) lives in buf[80&1] = buf0
    final_kernel<<<BB / 256, 256>>>(ph2, w_out, b_out, out);
}

// round 9
// speedup vs baseline: 1.7305x; 1.7305x over previous
#include <cuda_runtime.h>
#include <cuda_bf16.h>
#include <math.h>
#include <stdint.h>

#define BB 1024
#define TT 80
#define EE 100
#define UU 256
#define K1 384          // 256 (h1) + 128 (x padded)
#define K2 512          // 256 (h2) + 256 (h1)
#define NTOT 1024       // 4 gates * 256 units, permuted (see pack_w)
#define HS (UU*BB)

#define KC 64           // K-chunk
#define SASTR 72        // smem row stride in bf16 (144B; 36 words == 4 mod 32 -> conflict-free)
#define BUF_ELEMS (128*SASTR)
#define NBUF 3
// smem: A[3][128][72] bf16, B[3][128][72] bf16, bias[4][32] f32
#define SMEM_BYTES (2*NBUF*BUF_ELEMS*2 + 512)

// ---------------- device scratch ----------------
__device__ __nv_bfloat16 g_X[(size_t)TT * BB * 128];   // [t][b][e], e padded to 128
__device__ __nv_bfloat16 g_Wp1[(size_t)NTOT * K1];     // [n_packed][k]
__device__ __nv_bfloat16 g_Wp2[(size_t)NTOT * K2];
__device__ __nv_bfloat16 g_h1[2][HS];                  // [b][u]
__device__ __nv_bfloat16 g_h2[2][HS];
__device__ float g_c1[HS];                              // [b][u]
__device__ float g_c2[HS];

// ---------------- helpers ----------------
__device__ __forceinline__ float sigm(float x) {
    return __fdividef(1.0f, 1.0f + __expf(-x));
}
__device__ __forceinline__ float tanh_(float x) {
    return __fdividef(2.0f, 1.0f + __expf(-2.0f * x)) - 1.0f;
}
__device__ __forceinline__ void mma16(float* c, const uint32_t* a, const uint32_t* b) {
    asm volatile(
        "mma.sync.aligned.m16n8k16.row.col.f32.bf16.bf16.f32 "
        "{%0,%1,%2,%3}, {%4,%5,%6,%7}, {%8,%9}, {%0,%1,%2,%3};"
        : "+f"(c[0]), "+f"(c[1]), "+f"(c[2]), "+f"(c[3])
        : "r"(a[0]), "r"(a[1]), "r"(a[2]), "r"(a[3]), "r"(b[0]), "r"(b[1]));
}
__device__ __forceinline__ uint32_t smem_u32(const void* p) {
    uint32_t a;
    asm("{ .reg .u64 t; cvta.to.shared.u64 t, %1; cvt.u32.u64 %0, t; }" : "=r"(a) : "l"(p));
    return a;
}
__device__ __forceinline__ void cpasync16(uint32_t sdst, const void* gsrc) {
    asm volatile("cp.async.cg.shared.global [%0], [%1], 16;" :: "r"(sdst), "l"(gsrc));
}
__device__ __forceinline__ void cp_commit() {
    asm volatile("cp.async.commit_group;" ::: "memory");
}
__device__ __forceinline__ void cp_wait1() {
    asm volatile("cp.async.wait_group 1;" ::: "memory");
}
__device__ __forceinline__ void cp_wait0() {
    asm volatile("cp.async.wait_group 0;" ::: "memory");
}

// ---------------- init kernels ----------------
__global__ void gather_x(const int* __restrict__ tokens, const float* __restrict__ emb) {
    size_t idx = (size_t)blockIdx.x * 256 + threadIdx.x;
    if (idx >= (size_t)TT * BB * 128) return;
    int e = idx & 127;
    int b = (int)((idx >> 7) & (BB - 1));
    int t = (int)(idx >> 17);
    float v = 0.0f;
    if (e < EE) v = emb[(size_t)tokens[b * TT + t] * EE + e];
    g_X[idx] = __float2bfloat16(v);
}

// Packed layout: CTA n-tile = 128 cols = 4 warps x 32. Within a warp's 32 cols:
//   col = j*8 + q*2 + r,  j=0..3, q=0..3 (lane quad), r=0..1
//   unit_local = (j&1)*4 + q  (8 units per warp),  gate = (j>>1)*2 + r
__global__ void pack_w(const float* __restrict__ wf1, const float* __restrict__ wi1,
                       const float* __restrict__ wc1, const float* __restrict__ wo1,
                       const float* __restrict__ wf2, const float* __restrict__ wi2,
                       const float* __restrict__ wc2, const float* __restrict__ wo2) {
    int idx = blockIdx.x * 256 + threadIdx.x;
    const int tot1 = NTOT * K1;
    int P, k, which;
    if (idx < tot1) { P = idx / K1; k = idx % K1; which = 1; }
    else if (idx < tot1 + NTOT * K2) {
        int j2 = idx - tot1; P = j2 / K2; k = j2 % K2; which = 2;
    } else return;
    int ny  = P >> 7;
    int rem = P & 127;
    int wn  = rem >> 5;
    int col = rem & 31;
    int j = col >> 3, q = (col >> 1) & 3, r = col & 1;
    int u = ny * 32 + wn * 8 + (j & 1) * 4 + q;
    int g = (j >> 1) * 2 + r;
    if (which == 1) {
        float v = 0.0f;
        if (k < UU + EE) {
            const float* w = (g == 0) ? wf1 : (g == 1) ? wi1 : (g == 2) ? wc1 : wo1;
            v = w[(size_t)k * UU + u];
        }
        g_Wp1[idx] = __float2bfloat16(v);
    } else {
        const float* w = (g == 0) ? wf2 : (g == 1) ? wi2 : (g == 2) ? wc2 : wo2;
        g_Wp2[(size_t)P * K2 + k] = __float2bfloat16(w[(size_t)k * UU + u]);
    }
}

__global__ void zero_state() {
    int idx = blockIdx.x * 256 + threadIdx.x;
    if (idx < HS) {
        g_h1[0][idx] = __float2bfloat16(0.0f);
        g_h2[0][idx] = __float2bfloat16(0.0f);
        g_c1[idx] = 0.0f;
        g_c2[idx] = 0.0f;
    }
}

// ---------------- LSTM tile: 128 batch x 32 units x 4 gates, bf16 mma ----------------
template <int KP, int DX>
__device__ __forceinline__ void lstm_tile(
    const __nv_bfloat16* __restrict__ hI, const __nv_bfloat16* __restrict__ xI,
    const __nv_bfloat16* __restrict__ Wp,
    const float* __restrict__ bfv, const float* __restrict__ biv,
    const float* __restrict__ bcv, const float* __restrict__ bov,
    __nv_bfloat16* __restrict__ hO, float* __restrict__ cT,
    __nv_bfloat16* sa, __nv_bfloat16* sb, float* sBias) {

    const int tid  = threadIdx.x;
    const int lane = tid & 31, wid = tid >> 5;
    const int wm = wid >> 2, wn = wid & 3;       // 4m x 4n warps, warp tile 32m x 32n
    const int rr = lane >> 2, kq = lane & 3;
    const int b0 = blockIdx.x * 128;
    const int n0 = blockIdx.y * 128;             // packed-col base
    const int u0 = blockIdx.y * 32;              // unit base

    if (tid < 128) {
        int g = tid >> 5, ui = tid & 31;
        const float* bsrc = (g == 0) ? bfv : (g == 1) ? biv : (g == 2) ? bcv : bov;
        sBias[g * 32 + ui] = bsrc[u0 + ui];
    }

    constexpr int NC = KP / KC;

    // async loader: 512 threads; A/B tiles are 128 rows x 64 bf16 = 128 x 8 segs of 16B
    const int lrow = tid >> 2;
    const int ls4  = tid & 3;
    const uint32_t saBase = smem_u32(sa);
    const uint32_t sbBase = smem_u32(sb);

    auto prefetch = [&](int c) {
        const int buf = c % NBUF;
        const int kb = c * KC;
        const __nv_bfloat16* arow = (kb < UU)
            ? (hI + (size_t)(b0 + lrow) * UU + kb)
            : (xI + (size_t)(b0 + lrow) * DX + (kb - UU));
        const __nv_bfloat16* brow = Wp + (size_t)(n0 + lrow) * KP + kb;
        uint32_t sdA = saBase + (uint32_t)buf * (BUF_ELEMS * 2) + (uint32_t)lrow * (SASTR * 2);
        uint32_t sdB = sbBase + (uint32_t)buf * (BUF_ELEMS * 2) + (uint32_t)lrow * (SASTR * 2);
#pragma unroll
        for (int h = 0; h < 2; ++h) {
            int seg = ls4 + 4 * h;
            cpasync16(sdA + seg * 16, arow + seg * 8);
            cpasync16(sdB + seg * 16, brow + seg * 8);
        }
        cp_commit();
    };

    float acc[2][4][4];
#pragma unroll
    for (int mi = 0; mi < 2; ++mi)
#pragma unroll
        for (int j = 0; j < 4; ++j)
#pragma unroll
            for (int e = 0; e < 4; ++e) acc[mi][j][e] = 0.0f;

    prefetch(0);
    prefetch(1);

    for (int c = 0; c < NC; ++c) {
        if (c + 1 < NC) cp_wait1(); else cp_wait0();
        __syncthreads();
        if (c + 2 < NC) prefetch(c + 2);

        const __nv_bfloat16* sA = sa + (c % NBUF) * BUF_ELEMS;
        const __nv_bfloat16* sB = sb + (c % NBUF) * BUF_ELEMS;
#pragma unroll
        for (int ks = 0; ks < KC / 16; ++ks) {
            const int k0 = ks * 16;
            uint32_t a[2][4];
#pragma unroll
            for (int mi = 0; mi < 2; ++mi) {
                const int mr = wm * 32 + mi * 16 + rr;
                a[mi][0] = *(const uint32_t*)(sA + mr * SASTR + k0 + 2 * kq);
                a[mi][1] = *(const uint32_t*)(sA + (mr + 8) * SASTR + k0 + 2 * kq);
                a[mi][2] = *(const uint32_t*)(sA + mr * SASTR + k0 + 8 + 2 * kq);
                a[mi][3] = *(const uint32_t*)(sA + (mr + 8) * SASTR + k0 + 8 + 2 * kq);
            }
#pragma unroll
            for (int j = 0; j < 4; ++j) {
                const int nr = wn * 32 + j * 8 + rr;
                uint32_t b[2];
                b[0] = *(const uint32_t*)(sB + nr * SASTR + k0 + 2 * kq);
                b[1] = *(const uint32_t*)(sB + nr * SASTR + k0 + 8 + 2 * kq);
#pragma unroll
                for (int mi = 0; mi < 2; ++mi)
                    mma16(acc[mi][j], a[mi], b);
            }
        }
        // next prefetch targets buf (c+2)%3, never the buf being read; barrier at
        // top of next iteration protects buf reuse 3 iterations later.
    }

    // ---- epilogue: all 4 gates of each owned unit live in this lane's accs ----
    const int q = kq;
#pragma unroll
    for (int mi = 0; mi < 2; ++mi) {
#pragma unroll
        for (int ub = 0; ub < 2; ++ub) {
            const int u_in = wn * 8 + ub * 4 + q;
            const int u = u0 + u_in;
            const float bf_ = sBias[0 * 32 + u_in], bi_ = sBias[1 * 32 + u_in];
            const float bc_ = sBias[2 * 32 + u_in], bo_ = sBias[3 * 32 + u_in];
#pragma unroll
            for (int rh = 0; rh < 2; ++rh) {
                const int b = b0 + wm * 32 + mi * 16 + rh * 8 + rr;
                float pf = acc[mi][ub    ][rh * 2 + 0] + bf_;
                float pi = acc[mi][ub    ][rh * 2 + 1] + bi_;
                float pc = acc[mi][ub + 2][rh * 2 + 0] + bc_;
                float po = acc[mi][ub + 2][rh * 2 + 1] + bo_;
                size_t off = (size_t)b * UU + u;
                float cn = sigm(pf) * cT[off] + sigm(pi) * tanh_(pc);
                cT[off] = cn;
                hO[off] = __float2bfloat16(sigm(po) * tanh_(cn));
            }
        }
    }
}

// ---------------- fused step kernel: z=0 -> layer2(k-1), z=1 -> layer1(k) ----------------
__global__ __launch_bounds__(512, 1)
void step_kernel(
    int do1, const __nv_bfloat16* __restrict__ h1i, __nv_bfloat16* __restrict__ h1o,
    float* __restrict__ c1, const __nv_bfloat16* __restrict__ x1,
    const __nv_bfloat16* __restrict__ Wp1,
    const float* __restrict__ bf1, const float* __restrict__ bi1,
    const float* __restrict__ bc1, const float* __restrict__ bo1,
    int do2, const __nv_bfloat16* __restrict__ h2i, __nv_bfloat16* __restrict__ h2o,
    float* __restrict__ c2, const __nv_bfloat16* __restrict__ x2,
    const __nv_bfloat16* __restrict__ Wp2,
    const float* __restrict__ bf2, const float* __restrict__ bi2,
    const float* __restrict__ bc2, const float* __restrict__ bo2) {

    extern __shared__ __nv_bfloat16 smraw[];
    __nv_bfloat16* sa = smraw;
    __nv_bfloat16* sb = smraw + NBUF * BUF_ELEMS;
    float* sBias = (float*)(smraw + 2 * NBUF * BUF_ELEMS);

    if (blockIdx.z == 1) {
        if (!do1) return;
        lstm_tile<K1, 128>(h1i, x1, Wp1, bf1, bi1, bc1, bo1, h1o, c1, sa, sb, sBias);
    } else {
        if (!do2) return;
        lstm_tile<K2, 256>(h2i, x2, Wp2, bf2, bi2, bc2, bo2, h2o, c2, sa, sb, sBias);
    }
}

// ---------------- output head ----------------
__global__ void final_kernel(const __nv_bfloat16* __restrict__ h2,
                             const float* __restrict__ w_out,
                             const float* __restrict__ b_out,
                             float* __restrict__ out) {
    int b    = blockIdx.x * 8 + (threadIdx.x >> 5);
    int lane = threadIdx.x & 31;
    float s = 0.0f;
#pragma unroll
    for (int u = lane; u < UU; u += 32)
        s += __bfloat162float(h2[(size_t)b * UU + u]) * w_out[u];
#pragma unroll
    for (int off = 16; off; off >>= 1) s += __shfl_xor_sync(0xFFFFFFFFu, s, off);
    if (lane == 0) out[b] = __fdividef(1.0f, 1.0f + __expf(-(s + b_out[0])));
}

// ---------------- launch ----------------
extern "C" void kernel_launch(void* const* d_in, const int* in_sizes, int n_in,
                              void* d_out, int out_size) {
    const int*   tokens = (const int*)d_in[0];
    const float* emb    = (const float*)d_in[1];
    const float* wf1 = (const float*)d_in[2];  const float* bf1 = (const float*)d_in[3];
    const float* wi1 = (const float*)d_in[4];  const float* bi1 = (const float*)d_in[5];
    const float* wc1 = (const float*)d_in[6];  const float* bc1 = (const float*)d_in[7];
    const float* wo1 = (const float*)d_in[8];  const float* bo1 = (const float*)d_in[9];
    const float* wf2 = (const float*)d_in[10]; const float* bf2 = (const float*)d_in[11];
    const float* wi2 = (const float*)d_in[12]; const float* bi2 = (const float*)d_in[13];
    const float* wc2 = (const float*)d_in[14]; const float* bc2 = (const float*)d_in[15];
    const float* wo2 = (const float*)d_in[16]; const float* bo2 = (const float*)d_in[17];
    const float* w_out = (const float*)d_in[18];
    const float* b_out = (const float*)d_in[19];
    float* out = (float*)d_out;

    __nv_bfloat16 *pX, *pW1, *pW2, *ph1, *ph2;
    float *pc1, *pc2;
    cudaGetSymbolAddress((void**)&pX,  g_X);
    cudaGetSymbolAddress((void**)&pW1, g_Wp1);
    cudaGetSymbolAddress((void**)&pW2, g_Wp2);
    cudaGetSymbolAddress((void**)&ph1, g_h1);
    cudaGetSymbolAddress((void**)&ph2, g_h2);
    cudaGetSymbolAddress((void**)&pc1, g_c1);
    cudaGetSymbolAddress((void**)&pc2, g_c2);

    cudaFuncSetAttribute(step_kernel,
                         cudaFuncAttributeMaxDynamicSharedMemorySize, SMEM_BYTES);

    {
        size_t totx = (size_t)TT * BB * 128;
        gather_x<<<(unsigned)((totx + 255) / 256), 256>>>(tokens, emb);
        int totw = NTOT * K1 + NTOT * K2;
        pack_w<<<(totw + 255) / 256, 256>>>(wf1, wi1, wc1, wo1, wf2, wi2, wc2, wo2);
        zero_state<<<(HS + 255) / 256, 256>>>();
    }

    // Pipelined schedule: launch k runs layer1(step k) and layer2(step k-1).
    dim3 grid(BB / 128, NTOT / 128, 2);      // 8 x 8 x 2 = 128 CTAs, 512 thr
    for (int k = 0; k <= TT; k++) {
        int do1 = (k < TT) ? 1 : 0;
        int do2 = (k >= 1) ? 1 : 0;
        const __nv_bfloat16* h1i = ph1 + (k & 1) * HS;        // h1(k-1)
        __nv_bfloat16*       h1o = ph1 + ((k + 1) & 1) * HS;  // h1(k)
        const __nv_bfloat16* x1  = pX + (size_t)((k < TT) ? k : 0) * BB * 128;
        const __nv_bfloat16* h2i = ph2 + ((k + 1) & 1) * HS;  // h2(k-2)
        __nv_bfloat16*       h2o = ph2 + (k & 1) * HS;        // h2(k-1)
        const __nv_bfloat16* x2  = ph1 + (k & 1) * HS;        // h1(k-1)
        step_kernel<<<grid, 512, SMEM_BYTES>>>(
            do1, h1i, h1o, pc1, x1, pW1, bf1, bi1, bc1, bo1,
            do2, h2i, h2o, pc2, x2, pW2, bf2, bi2, bc2, bo2);
    }

    // h2(79) lives in buf[80&1] = buf0
    final_kernel<<<BB / 8, 256>>>(ph2, w_out, b_out, out);
}

// round 13
// speedup vs baseline: 1.9398x; 1.1210x over previous
#include <cuda_runtime.h>
#include <cuda_bf16.h>
#include <math.h>
#include <stdint.h>

#define BB 1024
#define TT 80
#define EE 100
#define UU 256
#define K1 384          // 256 (h1) + 128 (x padded)
#define K2 512          // 256 (h2) + 256 (h1)
#define NTOT 1024       // 4 gates * 256 units, permuted (see pack_w)
#define HS (UU*BB)

#define KC 64           // K-chunk for A streaming
#define SASTR 72        // A smem row stride bf16 (36 words == 4 mod 32 -> conflict-free)
#define ABUF (128*SASTR)
#define NBUF 3
#define WSTR1 (K1+8)    // 392 -> 196 words == 4 mod 32 -> conflict-free
#define WSTR2 (K2+8)    // 520 -> 260 words == 4 mod 32 -> conflict-free
#define SMEM_ELEMS (128*WSTR2 + NBUF*ABUF)
#define SMEM_BYTES (SMEM_ELEMS*2 + 512)

// ---------------- device scratch ----------------
__device__ __nv_bfloat16 g_X[(size_t)TT * BB * 128];   // [t][b][e], e padded to 128
__device__ __nv_bfloat16 g_Wp1[(size_t)NTOT * K1];     // [n_packed][k]
__device__ __nv_bfloat16 g_Wp2[(size_t)NTOT * K2];
__device__ __nv_bfloat16 g_h1[2][HS];                  // [b][u]
__device__ __nv_bfloat16 g_h2[2][HS];
__device__ float g_c1[HS];                              // [b][u]
__device__ float g_c2[HS];
__device__ unsigned g_bar[8 * 32];                      // 1 counter / batch group, 128B apart

// ---------------- helpers ----------------
__device__ __forceinline__ float sigm(float x) {
    return __fdividef(1.0f, 1.0f + __expf(-x));
}
__device__ __forceinline__ float tanh_(float x) {
    return __fdividef(2.0f, 1.0f + __expf(-2.0f * x)) - 1.0f;
}
__device__ __forceinline__ void mma16(float* c, const uint32_t* a, const uint32_t* b) {
    asm volatile(
        "mma.sync.aligned.m16n8k16.row.col.f32.bf16.bf16.f32 "
        "{%0,%1,%2,%3}, {%4,%5,%6,%7}, {%8,%9}, {%0,%1,%2,%3};"
        : "+f"(c[0]), "+f"(c[1]), "+f"(c[2]), "+f"(c[3])
        : "r"(a[0]), "r"(a[1]), "r"(a[2]), "r"(a[3]), "r"(b[0]), "r"(b[1]));
}
__device__ __forceinline__ uint32_t smem_u32(const void* p) {
    uint32_t a;
    asm("{ .reg .u64 t; cvta.to.shared.u64 t, %1; cvt.u32.u64 %0, t; }" : "=r"(a) : "l"(p));
    return a;
}
__device__ __forceinline__ void cpasync16(uint32_t sdst, const void* gsrc) {
    asm volatile("cp.async.cg.shared.global [%0], [%1], 16;" :: "r"(sdst), "l"(gsrc));
}
__device__ __forceinline__ void cp_commit() {
    asm volatile("cp.async.commit_group;" ::: "memory");
}
__device__ __forceinline__ void cp_wait1() {
    asm volatile("cp.async.wait_group 1;" ::: "memory");
}
__device__ __forceinline__ void cp_wait0() {
    asm volatile("cp.async.wait_group 0;" ::: "memory");
}

// ---------------- init kernels ----------------
__global__ void gather_x(const int* __restrict__ tokens, const float* __restrict__ emb) {
    size_t idx = (size_t)blockIdx.x * 256 + threadIdx.x;
    if (idx >= (size_t)TT * BB * 128) return;
    int e = idx & 127;
    int b = (int)((idx >> 7) & (BB - 1));
    int t = (int)(idx >> 17);
    float v = 0.0f;
    if (e < EE) v = emb[(size_t)tokens[b * TT + t] * EE + e];
    g_X[idx] = __float2bfloat16(v);
}

// Packed layout: CTA n-tile = 128 cols = 4 warps x 32. Within a warp's 32 cols:
//   col = j*8 + q*2 + r,  j=0..3, q=0..3 (lane quad), r=0..1
//   unit_local = (j&1)*4 + q  (8 units per warp),  gate = (j>>1)*2 + r
__global__ void pack_w(const float* __restrict__ wf1, const float* __restrict__ wi1,
                       const float* __restrict__ wc1, const float* __restrict__ wo1,
                       const float* __restrict__ wf2, const float* __restrict__ wi2,
                       const float* __restrict__ wc2, const float* __restrict__ wo2) {
    int idx = blockIdx.x * 256 + threadIdx.x;
    const int tot1 = NTOT * K1;
    int P, k, which;
    if (idx < tot1) { P = idx / K1; k = idx % K1; which = 1; }
    else if (idx < tot1 + NTOT * K2) {
        int j2 = idx - tot1; P = j2 / K2; k = j2 % K2; which = 2;
    } else return;
    int ny  = P >> 7;
    int rem = P & 127;
    int wn  = rem >> 5;
    int col = rem & 31;
    int j = col >> 3, q = (col >> 1) & 3, r = col & 1;
    int u = ny * 32 + wn * 8 + (j & 1) * 4 + q;
    int g = (j >> 1) * 2 + r;
    if (which == 1) {
        float v = 0.0f;
        if (k < UU + EE) {
            const float* w = (g == 0) ? wf1 : (g == 1) ? wi1 : (g == 2) ? wc1 : wo1;
            v = w[(size_t)k * UU + u];
        }
        g_Wp1[idx] = __float2bfloat16(v);
    } else {
        const float* w = (g == 0) ? wf2 : (g == 1) ? wi2 : (g == 2) ? wc2 : wo2;
        g_Wp2[(size_t)P * K2 + k] = __float2bfloat16(w[(size_t)k * UU + u]);
    }
}

__global__ void zero_state() {
    int idx = blockIdx.x * 256 + threadIdx.x;
    if (idx < HS) {
        g_h1[0][idx] = __float2bfloat16(0.0f);
        g_h2[0][idx] = __float2bfloat16(0.0f);
        g_c1[idx] = 0.0f;
        g_c2[idx] = 0.0f;
    }
    if (idx < 8 * 32) g_bar[idx] = 0u;
}

// ---------------- persistent LSTM worker ----------------
// Grid (8,8,2): x=batch block (128 rows), y=n block (32 units x 4 gates), z: 1=layer1, 0=layer2.
// All cross-iteration dependencies stay within one batch group (same blockIdx.x),
// so a 16-CTA group barrier per iteration suffices.
template <int KP, int DX, int LAYER1>
__device__ __forceinline__ void run_layer(
    const float* __restrict__ bfv, const float* __restrict__ biv,
    const float* __restrict__ bcv, const float* __restrict__ bov,
    __nv_bfloat16* sm) {

    constexpr int WSTR = KP + 8;
    constexpr int NC = KP / KC;
    __nv_bfloat16* sW = sm;
    __nv_bfloat16* sA = sm + 128 * WSTR;
    float* sBias = (float*)(sA + NBUF * ABUF);

    const int tid  = threadIdx.x;
    const int lane = tid & 31, wid = tid >> 5;
    const int wm = wid >> 2, wn = wid & 3;       // 4m x 4n warps, warp tile 32m x 32n
    const int rr = lane >> 2, kq = lane & 3;
    const int b0 = blockIdx.x * 128;
    const int n0 = blockIdx.y * 128;
    const int u0 = blockIdx.y * 32;
    unsigned* bar = &g_bar[blockIdx.x * 32];

    const uint32_t swB = smem_u32(sW);
    const uint32_t saB = smem_u32(sA);

    // ---- load weight tile into smem once (cp.async, waited by first chunk wait) ----
    {
        const __nv_bfloat16* Wp = LAYER1 ? g_Wp1 : g_Wp2;
        const int rowsegs = KP / 8;              // 16B segments per row
        for (int s = tid; s < 128 * rowsegs; s += 512) {
            int r = s / rowsegs, seg = s - r * rowsegs;
            cpasync16(swB + (uint32_t)(r * WSTR + seg * 8) * 2,
                      Wp + (size_t)(n0 + r) * KP + seg * 8);
        }
        cp_commit();
    }
    // ---- stage biases ----
    if (tid < 128) {
        int g = tid >> 5, ui = tid & 31;
        const float* bsrc = (g == 0) ? bfv : (g == 1) ? biv : (g == 2) ? bcv : bov;
        sBias[g * 32 + ui] = bsrc[u0 + ui];
    }

    const int lrow = tid >> 2;                   // A loader: row, 2 x 16B segs
    const int ls4  = tid & 3;

    for (int k = 0; k <= TT; ++k) {
        const bool active = LAYER1 ? (k < TT) : (k >= 1);
        if (active) {
            const __nv_bfloat16* hI;
            const __nv_bfloat16* xI;
            __nv_bfloat16* hO;
            float* cT;
            if (LAYER1) {
                hI = g_h1[k & 1];  xI = g_X + (size_t)k * BB * 128;
                hO = g_h1[(k + 1) & 1];  cT = g_c1;
            } else {
                hI = g_h2[(k + 1) & 1];  xI = g_h1[k & 1];
                hO = g_h2[k & 1];        cT = g_c2;
            }

            auto prefetchA = [&](int c) {
                const int kb = c * KC;
                const __nv_bfloat16* arow = (kb < UU)
                    ? (hI + (size_t)(b0 + lrow) * UU + kb)
                    : (xI + (size_t)(b0 + lrow) * DX + (kb - UU));
                uint32_t sd = saB + (uint32_t)((c % NBUF) * ABUF + lrow * SASTR) * 2;
#pragma unroll
                for (int h = 0; h < 2; ++h) {
                    int seg = ls4 + 4 * h;
                    cpasync16(sd + seg * 16, arow + seg * 8);
                }
                cp_commit();
            };

            float acc[2][4][4];
#pragma unroll
            for (int mi = 0; mi < 2; ++mi)
#pragma unroll
                for (int j = 0; j < 4; ++j)
#pragma unroll
                    for (int e = 0; e < 4; ++e) acc[mi][j][e] = 0.0f;

            prefetchA(0);
            prefetchA(1);

            for (int c = 0; c < NC; ++c) {
                if (c + 1 < NC) cp_wait1(); else cp_wait0();
                __syncthreads();
                if (c + 2 < NC) prefetchA(c + 2);

                const __nv_bfloat16* sAc = sA + (c % NBUF) * ABUF;
                const int kb = c * KC;
#pragma unroll
                for (int ks = 0; ks < KC / 16; ++ks) {
                    const int k0 = ks * 16;
                    uint32_t a[2][4];
#pragma unroll
                    for (int mi = 0; mi < 2; ++mi) {
                        const int mr = wm * 32 + mi * 16 + rr;
                        a[mi][0] = *(const uint32_t*)(sAc + mr * SASTR + k0 + 2 * kq);
                        a[mi][1] = *(const uint32_t*)(sAc + (mr + 8) * SASTR + k0 + 2 * kq);
                        a[mi][2] = *(const uint32_t*)(sAc + mr * SASTR + k0 + 8 + 2 * kq);
                        a[mi][3] = *(const uint32_t*)(sAc + (mr + 8) * SASTR + k0 + 8 + 2 * kq);
                    }
#pragma unroll
                    for (int j = 0; j < 4; ++j) {
                        const int nr = wn * 32 + j * 8 + rr;
                        uint32_t b[2];
                        b[0] = *(const uint32_t*)(sW + nr * WSTR + kb + k0 + 2 * kq);
                        b[1] = *(const uint32_t*)(sW + nr * WSTR + kb + k0 + 8 + 2 * kq);
#pragma unroll
                        for (int mi = 0; mi < 2; ++mi)
                            mma16(acc[mi][j], a[mi], b);
                    }
                }
            }

            // ---- epilogue: all 4 gates of each owned unit in this lane's accs ----
#pragma unroll
            for (int mi = 0; mi < 2; ++mi) {
#pragma unroll
                for (int ub = 0; ub < 2; ++ub) {
                    const int u_in = wn * 8 + ub * 4 + kq;
                    const int u = u0 + u_in;
                    const float bf_ = sBias[0 * 32 + u_in], bi_ = sBias[1 * 32 + u_in];
                    const float bc_ = sBias[2 * 32 + u_in], bo_ = sBias[3 * 32 + u_in];
#pragma unroll
                    for (int rh = 0; rh < 2; ++rh) {
                        const int b = b0 + wm * 32 + mi * 16 + rh * 8 + rr;
                        float pf = acc[mi][ub    ][rh * 2 + 0] + bf_;
                        float pi = acc[mi][ub    ][rh * 2 + 1] + bi_;
                        float pc = acc[mi][ub + 2][rh * 2 + 0] + bc_;
                        float po = acc[mi][ub + 2][rh * 2 + 1] + bo_;
                        size_t off = (size_t)b * UU + u;
                        float cn = sigm(pf) * cT[off] + sigm(pi) * tanh_(pc);
                        cT[off] = cn;
                        hO[off] = __float2bfloat16(sigm(po) * tanh_(cn));
                    }
                }
            }
        }

        // ---- group barrier (16 CTAs sharing this batch block) ----
        __syncthreads();
        if (tid == 0) {
            __threadfence();
            atomicAdd(bar, 1u);
            const unsigned tgt = 16u * (unsigned)(k + 1);
            while (*(volatile unsigned*)bar < tgt) { }
            __threadfence();
        }
        __syncthreads();
    }
}

__global__ __launch_bounds__(512, 1)
void lstm_persist(
    const float* __restrict__ bf1, const float* __restrict__ bi1,
    const float* __restrict__ bc1, const float* __restrict__ bo1,
    const float* __restrict__ bf2, const float* __restrict__ bi2,
    const float* __restrict__ bc2, const float* __restrict__ bo2) {
    extern __shared__ __nv_bfloat16 sm[];
    if (blockIdx.z == 1) run_layer<K1, 128, 1>(bf1, bi1, bc1, bo1, sm);
    else                 run_layer<K2, 256, 0>(bf2, bi2, bc2, bo2, sm);
}

// ---------------- output head ----------------
__global__ void final_kernel(const float* __restrict__ w_out,
                             const float* __restrict__ b_out,
                             float* __restrict__ out) {
    int b    = blockIdx.x * 8 + (threadIdx.x >> 5);
    int lane = threadIdx.x & 31;
    const __nv_bfloat16* h2 = g_h2[0];           // h2(79) lives in buf[80&1] = buf0
    float s = 0.0f;
#pragma unroll
    for (int u = lane; u < UU; u += 32)
        s += __bfloat162float(h2[(size_t)b * UU + u]) * w_out[u];
#pragma unroll
    for (int off = 16; off; off >>= 1) s += __shfl_xor_sync(0xFFFFFFFFu, s, off);
    if (lane == 0) out[b] = __fdividef(1.0f, 1.0f + __expf(-(s + b_out[0])));
}

// ---------------- launch ----------------
extern "C" void kernel_launch(void* const* d_in, const int* in_sizes, int n_in,
                              void* d_out, int out_size) {
    const int*   tokens = (const int*)d_in[0];
    const float* emb    = (const float*)d_in[1];
    const float* wf1 = (const float*)d_in[2];  const float* bf1 = (const float*)d_in[3];
    const float* wi1 = (const float*)d_in[4];  const float* bi1 = (const float*)d_in[5];
    const float* wc1 = (const float*)d_in[6];  const float* bc1 = (const float*)d_in[7];
    const float* wo1 = (const float*)d_in[8];  const float* bo1 = (const float*)d_in[9];
    const float* wf2 = (const float*)d_in[10]; const float* bf2 = (const float*)d_in[11];
    const float* wi2 = (const float*)d_in[12]; const float* bi2 = (const float*)d_in[13];
    const float* wc2 = (const float*)d_in[14]; const float* bc2 = (const float*)d_in[15];
    const float* wo2 = (const float*)d_in[16]; const float* bo2 = (const float*)d_in[17];
    const float* w_out = (const float*)d_in[18];
    const float* b_out = (const float*)d_in[19];
    float* out = (float*)d_out;

    cudaFuncSetAttribute(lstm_persist,
                         cudaFuncAttributeMaxDynamicSharedMemorySize, SMEM_BYTES);

    {
        size_t totx = (size_t)TT * BB * 128;
        gather_x<<<(unsigned)((totx + 255) / 256), 256>>>(tokens, emb);
        int totw = NTOT * K1 + NTOT * K2;
        pack_w<<<(totw + 255) / 256, 256>>>(wf1, wi1, wc1, wo1, wf2, wi2, wc2, wo2);
        zero_state<<<(HS + 255) / 256, 256>>>();
    }

    dim3 grid(BB / 128, NTOT / 128, 2);      // 8 x 8 x 2 = 128 persistent CTAs
    lstm_persist<<<grid, 512, SMEM_BYTES>>>(bf1, bi1, bc1, bo1, bf2, bi2, bc2, bo2);

    final_kernel<<<BB / 8, 256>>>(w_out, b_out, out);
}

// round 15
// speedup vs baseline: 2.4094x; 1.2421x over previous
#include <cuda_runtime.h>
#include <cuda_bf16.h>
#include <math.h>
#include <stdint.h>

#define BB 1024
#define TT 80
#define EE 100
#define UU 256
#define K1 384          // 256 (h1) + 128 (x padded)
#define K2 512          // 256 (h2) + 256 (h1)
#define NTOT 1024       // 4 gates * 256 units, permuted (see pack_w)
#define HS (UU*BB)

#define KC 64           // K-chunk for A streaming
#define SASTR 72        // A smem row stride bf16 (36 words == 4 mod 32 -> conflict-free)
#define ABUF (128*SASTR)
#define NBUF 3
#define WSTR1 (K1+8)    // 392 el -> 196 words == 4 mod 32 -> conflict-free
#define WSTR2 (K2+8)    // 520 el -> 260 words == 4 mod 32 -> conflict-free
#define SMEM_ELEMS (128*WSTR2 + NBUF*ABUF)
#define SMEM_BYTES (SMEM_ELEMS*2 + 512)

// ---------------- device scratch ----------------
__device__ __nv_bfloat16 g_X[(size_t)TT * BB * 128];   // [t][b][e], e padded to 128
__device__ __nv_bfloat16 g_Wp1[(size_t)NTOT * K1];     // [n_packed][k]
__device__ __nv_bfloat16 g_Wp2[(size_t)NTOT * K2];
__device__ __nv_bfloat16 g_h1[2][HS];                  // [b][u]
__device__ __nv_bfloat16 g_h2[2][HS];
__device__ unsigned g_bar[8 * 32];                      // 1 counter / batch group, 128B apart

// ---------------- helpers ----------------
__device__ __forceinline__ float sigm(float x) {
    return __fdividef(1.0f, 1.0f + __expf(-x));
}
__device__ __forceinline__ float tanh_(float x) {
    return __fdividef(2.0f, 1.0f + __expf(-2.0f * x)) - 1.0f;
}
__device__ __forceinline__ void mma16(float* c, const uint32_t* a, const uint32_t* b) {
    asm volatile(
        "mma.sync.aligned.m16n8k16.row.col.f32.bf16.bf16.f32 "
        "{%0,%1,%2,%3}, {%4,%5,%6,%7}, {%8,%9}, {%0,%1,%2,%3};"
        : "+f"(c[0]), "+f"(c[1]), "+f"(c[2]), "+f"(c[3])
        : "r"(a[0]), "r"(a[1]), "r"(a[2]), "r"(a[3]), "r"(b[0]), "r"(b[1]));
}
__device__ __forceinline__ void ldsm4(uint32_t* r, uint32_t addr) {
    asm volatile("ldmatrix.sync.aligned.m8n8.x4.shared.b16 {%0,%1,%2,%3}, [%4];"
        : "=r"(r[0]), "=r"(r[1]), "=r"(r[2]), "=r"(r[3]) : "r"(addr));
}
__device__ __forceinline__ uint32_t smem_u32(const void* p) {
    uint32_t a;
    asm("{ .reg .u64 t; cvta.to.shared.u64 t, %1; cvt.u32.u64 %0, t; }" : "=r"(a) : "l"(p));
    return a;
}
__device__ __forceinline__ void cpasync16(uint32_t sdst, const void* gsrc) {
    asm volatile("cp.async.cg.shared.global [%0], [%1], 16;" :: "r"(sdst), "l"(gsrc));
}
__device__ __forceinline__ void cp_commit() {
    asm volatile("cp.async.commit_group;" ::: "memory");
}
__device__ __forceinline__ void cp_wait1() {
    asm volatile("cp.async.wait_group 1;" ::: "memory");
}
__device__ __forceinline__ void cp_wait0() {
    asm volatile("cp.async.wait_group 0;" ::: "memory");
}

// ---------------- init kernels ----------------
__global__ void gather_x(const int* __restrict__ tokens, const float* __restrict__ emb) {
    size_t idx = (size_t)blockIdx.x * 256 + threadIdx.x;
    if (idx >= (size_t)TT * BB * 128) return;
    int e = idx & 127;
    int b = (int)((idx >> 7) & (BB - 1));
    int t = (int)(idx >> 17);
    float v = 0.0f;
    if (e < EE) v = emb[(size_t)tokens[b * TT + t] * EE + e];
    g_X[idx] = __float2bfloat16(v);
}

// Packed layout: CTA n-tile = 128 cols = 4 n-warps x 32. Within a warp's 32 cols:
//   col = j*8 + q*2 + r,  j=0..3, q=0..3 (lane quad), r=0..1
//   unit_local = (j&1)*4 + q  (8 units per n-warp),  gate = (j>>1)*2 + r
__global__ void pack_w(const float* __restrict__ wf1, const float* __restrict__ wi1,
                       const float* __restrict__ wc1, const float* __restrict__ wo1,
                       const float* __restrict__ wf2, const float* __restrict__ wi2,
                       const float* __restrict__ wc2, const float* __restrict__ wo2) {
    int idx = blockIdx.x * 256 + threadIdx.x;
    const int tot1 = NTOT * K1;
    int P, k, which;
    if (idx < tot1) { P = idx / K1; k = idx % K1; which = 1; }
    else if (idx < tot1 + NTOT * K2) {
        int j2 = idx - tot1; P = j2 / K2; k = j2 % K2; which = 2;
    } else return;
    int ny  = P >> 7;
    int rem = P & 127;
    int wn  = rem >> 5;
    int col = rem & 31;
    int j = col >> 3, q = (col >> 1) & 3, r = col & 1;
    int u = ny * 32 + wn * 8 + (j & 1) * 4 + q;
    int g = (j >> 1) * 2 + r;
    if (which == 1) {
        float v = 0.0f;
        if (k < UU + EE) {
            const float* w = (g == 0) ? wf1 : (g == 1) ? wi1 : (g == 2) ? wc1 : wo1;
            v = w[(size_t)k * UU + u];
        }
        g_Wp1[idx] = __float2bfloat16(v);
    } else {
        const float* w = (g == 0) ? wf2 : (g == 1) ? wi2 : (g == 2) ? wc2 : wo2;
        g_Wp2[(size_t)P * K2 + k] = __float2bfloat16(w[(size_t)k * UU + u]);
    }
}

__global__ void zero_state() {
    int idx = blockIdx.x * 256 + threadIdx.x;
    if (idx < HS) {
        g_h1[0][idx] = __float2bfloat16(0.0f);
        g_h2[0][idx] = __float2bfloat16(0.0f);
    }
    if (idx < 8 * 32) g_bar[idx] = 0u;
}

// ---------------- persistent LSTM worker ----------------
// Grid (8,8,2): x=batch block (128 rows), y=n block (32 units x 4 gates), z: 1=layer1, 0=layer2.
// 1024 threads = 32 warps: wm=wid>>2 (8 m-warps of 16 rows), wn=wid&3 (4 n-warps of 32 cols).
// c-state lives in registers (same CTA owns the same (b,u) cells for all 80 steps).
template <int KP, int DX, int LAYER1>
__device__ __forceinline__ void run_layer(
    const float* __restrict__ bfv, const float* __restrict__ biv,
    const float* __restrict__ bcv, const float* __restrict__ bov,
    __nv_bfloat16* sm) {

    constexpr int WSTR = KP + 8;
    constexpr int NC = KP / KC;
    __nv_bfloat16* sW = sm;
    __nv_bfloat16* sA = sm + 128 * WSTR;
    float* sBias = (float*)(sA + NBUF * ABUF);

    const int tid  = threadIdx.x;
    const int lane = tid & 31, wid = tid >> 5;
    const int wm = wid >> 2, wn = wid & 3;
    const int rr = lane >> 2, kq = lane & 3;
    const int b0 = blockIdx.x * 128;
    const int n0 = blockIdx.y * 128;
    const int u0 = blockIdx.y * 32;
    unsigned* bar = &g_bar[blockIdx.x * 32];

    const uint32_t swB = smem_u32(sW);
    const uint32_t saB = smem_u32(sA);

    // ---- load weight tile into smem once ----
    {
        const __nv_bfloat16* Wp = LAYER1 ? g_Wp1 : g_Wp2;
        const int rowsegs = KP / 8;
        for (int s = tid; s < 128 * rowsegs; s += 1024) {
            int r = s / rowsegs, seg = s - r * rowsegs;
            cpasync16(swB + (uint32_t)(r * WSTR + seg * 8) * 2,
                      Wp + (size_t)(n0 + r) * KP + seg * 8);
        }
        cp_commit();
    }
    if (tid < 128) {
        int g = tid >> 5, ui = tid & 31;
        const float* bsrc = (g == 0) ? bfv : (g == 1) ? biv : (g == 2) ? bcv : bov;
        sBias[g * 32 + ui] = bsrc[u0 + ui];
    }

    // ---- per-lane ldmatrix addresses ----
    // A (m16k16, x4: m0k0, m8k0, m0k8, m8k8):
    const uint32_t aOff = (uint32_t)((wm * 16 + (lane & 7) + ((lane >> 3) & 1) * 8) * SASTR
                                     + ((lane >> 4) & 1) * 8) * 2;
    // B (two n8k16 tiles, x4: j,k0 / j,k8 / j+1,k0 / j+1,k8):
    uint32_t wOff[2];
#pragma unroll
    for (int jp = 0; jp < 2; ++jp)
        wOff[jp] = (uint32_t)((wn * 32 + jp * 16 + (lane & 7) + ((lane >> 4) & 1) * 8) * WSTR
                              + ((lane >> 3) & 1) * 8) * 2;

    // A-chunk loader: 1024 threads x 16B = 16KB chunk
    const int lrow = tid >> 3;
    const int lseg = tid & 7;

    // ---- register-resident cell state: c[ub*2+rh] ----
    float c_reg[4] = {0.0f, 0.0f, 0.0f, 0.0f};

    for (int k = 0; k <= TT; ++k) {
        const bool active = LAYER1 ? (k < TT) : (k >= 1);
        if (active) {
            const __nv_bfloat16* hI;
            const __nv_bfloat16* xI;
            __nv_bfloat16* hO;
            if (LAYER1) {
                hI = g_h1[k & 1];  xI = g_X + (size_t)k * BB * 128;
                hO = g_h1[(k + 1) & 1];
            } else {
                hI = g_h2[(k + 1) & 1];  xI = g_h1[k & 1];
                hO = g_h2[k & 1];
            }

            auto prefetchA = [&](int c) {
                const int kb = c * KC;
                const __nv_bfloat16* arow = (kb < UU)
                    ? (hI + (size_t)(b0 + lrow) * UU + kb)
                    : (xI + (size_t)(b0 + lrow) * DX + (kb - UU));
                uint32_t sd = saB + (uint32_t)((c % NBUF) * ABUF + lrow * SASTR + lseg * 8) * 2;
                cpasync16(sd, arow + lseg * 8);
                cp_commit();
            };

            float acc[4][4];
#pragma unroll
            for (int j = 0; j < 4; ++j)
#pragma unroll
                for (int e = 0; e < 4; ++e) acc[j][e] = 0.0f;

            prefetchA(0);
            prefetchA(1);

            for (int c = 0; c < NC; ++c) {
                if (c + 1 < NC) cp_wait1(); else cp_wait0();
                __syncthreads();
                if (c + 2 < NC) prefetchA(c + 2);

                const uint32_t aBase = saB + (uint32_t)((c % NBUF) * ABUF) * 2 + aOff;
                const uint32_t kb2 = (uint32_t)(c * KC) * 2;
#pragma unroll
                for (int ks = 0; ks < KC / 16; ++ks) {
                    const uint32_t k0b = (uint32_t)(ks * 16) * 2;
                    uint32_t a[4];
                    ldsm4(a, aBase + k0b);
#pragma unroll
                    for (int jp = 0; jp < 2; ++jp) {
                        uint32_t b4[4];
                        ldsm4(b4, swB + wOff[jp] + kb2 + k0b);
                        mma16(acc[jp * 2 + 0], a, b4 + 0);
                        mma16(acc[jp * 2 + 1], a, b4 + 2);
                    }
                }
            }

            // ---- epilogue: 2 units x 2 rows per thread, c in registers ----
#pragma unroll
            for (int ub = 0; ub < 2; ++ub) {
                const int u_in = wn * 8 + ub * 4 + kq;
                const int u = u0 + u_in;
                const float bf_ = sBias[0 * 32 + u_in], bi_ = sBias[1 * 32 + u_in];
                const float bc_ = sBias[2 * 32 + u_in], bo_ = sBias[3 * 32 + u_in];
#pragma unroll
                for (int rh = 0; rh < 2; ++rh) {
                    const int b = b0 + wm * 16 + rh * 8 + rr;
                    float pf = acc[ub    ][rh * 2 + 0] + bf_;
                    float pi = acc[ub    ][rh * 2 + 1] + bi_;
                    float pc = acc[ub + 2][rh * 2 + 0] + bc_;
                    float po = acc[ub + 2][rh * 2 + 1] + bo_;
                    float cn = sigm(pf) * c_reg[ub * 2 + rh] + sigm(pi) * tanh_(pc);
                    c_reg[ub * 2 + rh] = cn;
                    hO[(size_t)b * UU + u] = __float2bfloat16(sigm(po) * tanh_(cn));
                }
            }
        }

        // ---- group barrier (16 CTAs sharing this batch block) ----
        __syncthreads();
        if (tid == 0) {
            __threadfence();
            atomicAdd(bar, 1u);
            const unsigned tgt = 16u * (unsigned)(k + 1);
            while (*(volatile unsigned*)bar < tgt) { }
            __threadfence();
        }
        __syncthreads();
    }
}

__global__ __launch_bounds__(1024, 1)
void lstm_persist(
    const float* __restrict__ bf1, const float* __restrict__ bi1,
    const float* __restrict__ bc1, const float* __restrict__ bo1,
    const float* __restrict__ bf2, const float* __restrict__ bi2,
    const float* __restrict__ bc2, const float* __restrict__ bo2) {
    extern __shared__ __nv_bfloat16 sm[];
    if (blockIdx.z == 1) run_layer<K1, 128, 1>(bf1, bi1, bc1, bo1, sm);
    else                 run_layer<K2, 256, 0>(bf2, bi2, bc2, bo2, sm);
}

// ---------------- output head ----------------
__global__ void final_kernel(const float* __restrict__ w_out,
                             const float* __restrict__ b_out,
                             float* __restrict__ out) {
    int b    = blockIdx.x * 8 + (threadIdx.x >> 5);
    int lane = threadIdx.x & 31;
    const __nv_bfloat16* h2 = g_h2[0];           // h2(79) lives in buf[80&1] = buf0
    float s = 0.0f;
#pragma unroll
    for (int u = lane; u < UU; u += 32)
        s += __bfloat162float(h2[(size_t)b * UU + u]) * w_out[u];
#pragma unroll
    for (int off = 16; off; off >>= 1) s += __shfl_xor_sync(0xFFFFFFFFu, s, off);
    if (lane == 0) out[b] = __fdividef(1.0f, 1.0f + __expf(-(s + b_out[0])));
}

// ---------------- launch ----------------
extern "C" void kernel_launch(void* const* d_in, const int* in_sizes, int n_in,
                              void* d_out, int out_size) {
    const int*   tokens = (const int*)d_in[0];
    const float* emb    = (const float*)d_in[1];
    const float* wf1 = (const float*)d_in[2];  const float* bf1 = (const float*)d_in[3];
    const float* wi1 = (const float*)d_in[4];  const float* bi1 = (const float*)d_in[5];
    const float* wc1 = (const float*)d_in[6];  const float* bc1 = (const float*)d_in[7];
    const float* wo1 = (const float*)d_in[8];  const float* bo1 = (const float*)d_in[9];
    const float* wf2 = (const float*)d_in[10]; const float* bf2 = (const float*)d_in[11];
    const float* wi2 = (const float*)d_in[12]; const float* bi2 = (const float*)d_in[13];
    const float* wc2 = (const float*)d_in[14]; const float* bc2 = (const float*)d_in[15];
    const float* wo2 = (const float*)d_in[16]; const float* bo2 = (const float*)d_in[17];
    const float* w_out = (const float*)d_in[18];
    const float* b_out = (const float*)d_in[19];
    float* out = (float*)d_out;

    cudaFuncSetAttribute(lstm_persist,
                         cudaFuncAttributeMaxDynamicSharedMemorySize, SMEM_BYTES);

    {
        size_t totx = (size_t)TT * BB * 128;
        gather_x<<<(unsigned)((totx + 255) / 256), 256>>>(tokens, emb);
        int totw = NTOT * K1 + NTOT * K2;
        pack_w<<<(totw + 255) / 256, 256>>>(wf1, wi1, wc1, wo1, wf2, wi2, wc2, wo2);
        zero_state<<<(HS + 255) / 256, 256>>>();
    }

    dim3 grid(BB / 128, NTOT / 128, 2);      // 8 x 8 x 2 = 128 persistent CTAs
    lstm_persist<<<grid, 1024, SMEM_BYTES>>>(bf1, bi1, bc1, bo1, bf2, bi2, bc2, bo2);

    final_kernel<<<BB / 8, 256>>>(w_out, b_out, out);
}